// round 7
// baseline (speedup 1.0000x reference)
#include <cuda_runtime.h>
#include <cuda_bf16.h>

// GLRK 4th-order (2-stage Gauss-Legendre) implicit step, B=8192, D=64.
// Picard iteration:  k1 = A1*(y0 + h*(a11 k1 + a12 k2)),
//                    k2 = A2*(y0 + h*(a21 k1 + a22 k2));  8 iters -> fp32 noise.
//
// R6 vs R2 (95.7us best): remove the smem staging buffer entirely.
// Each thread's 2x32 tile is private, so it is loaded straight from global
// into registers (16 LDG.128; the 8-wide unroll consumes every 128B line
// fully) with NO barrier between load and first use. The A copy is stored
// from the same registers. Shared memory shrinks to ~1KB (w/k/y only), so
// the whole-CTA wait-for-64KB convoy point disappears. Loop body, layout,
// reduction and natural register allocation are the proven R2 ones.

#define DD 64
#define NITER 8
#define WPAD 36   // second w half offset (bank shift, 16B aligned)

__global__ void __launch_bounds__(128)
glrk4_kernel(const float* __restrict__ gA1,
             const float* __restrict__ gA2,
             const float* __restrict__ gy0,
             const float* __restrict__ gh,
             float* __restrict__ outY,
             float* __restrict__ outA1,
             float* __restrict__ outA2)
{
    __shared__ __align__(16) float y0s[DD];
    __shared__ __align__(16) float w1s[2 * WPAD];
    __shared__ __align__(16) float w2s[2 * WPAD];
    __shared__ __align__(16) float k1s[DD];
    __shared__ __align__(16) float k2s[DD];

    const int tid = threadIdx.x;
    const size_t b = blockIdx.x;
    const float h = __ldg(gh);

    // Thread (p, hf): rows {2p, 2p+1} (p<32 -> A1 else A2), cols [32hf,32hf+32)
    const int p  = tid >> 1;
    const int hf = tid & 1;
    const bool isA1 = (p < 32);
    const int r0 = (isA1 ? p : (p - 32)) << 1;

    // Load private tile straight from global into registers.
    // float4 row stride = 16; this thread's half-rows start at r0*16 + hf*8.
    const float4* g = (const float4*)((isA1 ? gA1 : gA2) + b * (DD * DD));
    const float4* pa = g + r0 * 16 + (hf << 3);
    float4 ra[8], rb[8];
    #pragma unroll
    for (int m = 0; m < 8; m++) ra[m] = pa[m];
    #pragma unroll
    for (int m = 0; m < 8; m++) rb[m] = pa[16 + m];

    // w init (w = y0 -> first matvec gives k = R)
    if (tid < DD) {
        float yv = gy0[b * DD + tid];
        y0s[tid] = yv;
        const int wi = (tid & 31) + ((tid >> 5) ? WPAD : 0);
        w1s[wi] = yv;
        w2s[wi] = yv;
    }

    // Copy A out straight from the tile registers (two 128B runs per lane).
    {
        float4* o = (float4*)((isA1 ? outA1 : outA2) + b * (DD * DD));
        float4* oa = o + r0 * 16 + (hf << 3);
        #pragma unroll
        for (int m = 0; m < 8; m++) oa[m] = ra[m];
        #pragma unroll
        for (int m = 0; m < 8; m++) oa[16 + m] = rb[m];
    }
    __syncthreads();   // w/y0 visible to everyone

    const float4* ws = (const float4*)((isA1 ? w1s : w2s) + hf * WPAD);
    float* ks = isA1 ? k1s : k2s;

    const float cA11 = 0.25f;
    const float cA12 = 0.25f - 0.288675134594812882f;  // 1/4 - sqrt(3)/6
    const float cA21 = 0.25f + 0.288675134594812882f;  // 1/4 + sqrt(3)/6
    const float cA22 = 0.25f;

    #pragma unroll 1
    for (int it = 0; it < NITER; it++) {
        float a0 = 0.f, a1 = 0.f, a2 = 0.f, a3 = 0.f;
        float b0 = 0.f, b1 = 0.f, b2 = 0.f, b3 = 0.f;
        #pragma unroll
        for (int m = 0; m < 8; m++) {
            float4 w = ws[m];              // broadcast LDS.128, conflict-free
            a0 = fmaf(ra[m].x, w.x, a0);
            a1 = fmaf(ra[m].y, w.y, a1);
            a2 = fmaf(ra[m].z, w.z, a2);
            a3 = fmaf(ra[m].w, w.w, a3);
            b0 = fmaf(rb[m].x, w.x, b0);
            b1 = fmaf(rb[m].y, w.y, b1);
            b2 = fmaf(rb[m].z, w.z, b2);
            b3 = fmaf(rb[m].w, w.w, b3);
        }
        float sa = (a0 + a1) + (a2 + a3);
        float sb = (b0 + b1) + (b2 + b3);
        sa += __shfl_xor_sync(0xffffffffu, sa, 1);   // combine half-rows
        sb += __shfl_xor_sync(0xffffffffu, sb, 1);
        ks[r0 + hf] = hf ? sb : sa;
        __syncthreads();

        if (it < NITER - 1) {
            if (tid < DD) {
                float k1 = k1s[tid];
                float k2 = k2s[tid];
                float y  = y0s[tid];
                const int wi = (tid & 31) + ((tid >> 5) ? WPAD : 0);
                w1s[wi] = fmaf(h, fmaf(cA11, k1, cA12 * k2), y);
                w2s[wi] = fmaf(h, fmaf(cA21, k1, cA22 * k2), y);
            }
            __syncthreads();
        }
    }

    if (tid < DD) {
        // y_next = y0 + h*(0.5*k1 + 0.5*k2)
        outY[b * DD + tid] = fmaf(h, 0.5f * (k1s[tid] + k2s[tid]), y0s[tid]);
    }
}

extern "C" void kernel_launch(void* const* d_in, const int* in_sizes, int n_in,
                              void* d_out, int out_size)
{
    const float* A1 = (const float*)d_in[0];   // [B, 64, 64]
    const float* A2 = (const float*)d_in[1];   // [B, 64, 64]
    const float* y0 = (const float*)d_in[2];   // [B, 64]
    const float* h  = (const float*)d_in[3];   // scalar

    float* out  = (float*)d_out;
    const size_t yElems = (size_t)in_sizes[2];         // B*64
    const size_t aElems = (size_t)in_sizes[0];         // B*64*64
    float* outY  = out;                                 // (B, 64)
    float* outA1 = out + yElems;                        // stack[0] = A1
    float* outA2 = outA1 + aElems;                      // stack[1] = A2

    const int B = (int)(yElems / DD);
    glrk4_kernel<<<B, 128>>>(A1, A2, y0, h, outY, outA1, outA2);
    (void)n_in; (void)out_size;
}

// round 8
// speedup vs baseline: 1.8543x; 1.8543x over previous
#include <cuda_runtime.h>
#include <cuda_bf16.h>

// GLRK 4th-order (2-stage Gauss-Legendre) implicit step, B=8192, D=64.
// Picard iteration:  k1 = A1*(y0 + h*(a11 k1 + a12 k2)),
//                    k2 = A2*(y0 + h*(a21 k1 + a22 k2))
//
// R8 = R2 (95.7us, the proven coalesced-staging kernel) with the compute
// phase halved:
//  - lane-interleaved pairing: lane bits (j3, hf=bit3, ai=bit4); thread owns
//    matrix ai, rows {j, j+8}, col-half hf. shfl_xor(8) combines col-halves,
//    shfl_xor(16) swaps matrices IN-WARP, so every thread computes its own
//    w entry -> ONE __syncthreads per iteration, no serial w-update phase.
//  - NITER 6 (7 iters already measured at the fp32 noise floor).
// Staging + register-tile + copy-out are exactly R2's (R6 proved direct LDG
// of the private tile destroys per-instruction coalescing).

#define DD 64
#define NITER 6
#define ROWPAD 68    // A staging row stride (16B aligned)
#define W2OFF 80     // w2 base offset in wbuf: 80 mod 32 = 16 -> STS conflict-free
#define WH 36        // half-stride within a w vector (bank shift by 4)

__global__ void __launch_bounds__(128)
glrk4_kernel(const float* __restrict__ gA1,
             const float* __restrict__ gA2,
             const float* __restrict__ gy0,
             const float* __restrict__ gh,
             float* __restrict__ outY,
             float* __restrict__ outA1,
             float* __restrict__ outA2)
{
    __shared__ __align__(16) float buf1[DD][ROWPAD];
    __shared__ __align__(16) float buf2[DD][ROWPAD];
    __shared__ __align__(16) float y0s[DD];
    __shared__ __align__(16) float wbuf[W2OFF + 2 * WH];  // w1 @0, w2 @80
    __shared__ __align__(16) float k1s[DD];
    __shared__ __align__(16) float k2s[DD];

    const int tid = threadIdx.x;
    const size_t b = blockIdx.x;
    const float h = __ldg(gh);

    const float4* g1 = (const float4*)(gA1 + b * (DD * DD));
    const float4* g2 = (const float4*)(gA2 + b * (DD * DD));
    float4* o1 = (float4*)(outA1 + b * (DD * DD));
    float4* o2 = (float4*)(outA2 + b * (DD * DD));

    // Coalesced staging of A1/A2 into padded smem + fused output copy.
    #pragma unroll
    for (int i = tid; i < DD * DD / 4; i += 128) {
        const int row = i >> 4;
        const int c   = (i & 15) << 2;
        float4 v1 = g1[i];
        *(float4*)&buf1[row][c] = v1;
        o1[i] = v1;
        float4 v2 = g2[i];
        *(float4*)&buf2[row][c] = v2;
        o2[i] = v2;
    }
    if (tid < DD) {
        float yv = gy0[b * DD + tid];
        y0s[tid] = yv;
        const int wi = (tid >> 5) * WH + (tid & 31);
        wbuf[wi] = yv;            // w1 = y0  (first matvec -> k = R)
        wbuf[W2OFF + wi] = yv;    // w2 = y0
    }
    __syncthreads();

    // Lane mapping: j3 = lane[2:0], hf = lane[3], ai = lane[4].
    const int lane = tid & 31;
    const int wrp  = tid >> 5;
    const int j3 = lane & 7;
    const int hf = (lane >> 3) & 1;
    const int ai = (lane >> 4) & 1;
    const int j  = wrp * 16 + j3;          // owns rows j and j+8 of matrix ai

    float4 ra[8], rb[8];
    {
        const float (*bufp)[ROWPAD] = ai ? buf2 : buf1;
        const float4* pa = (const float4*)&bufp[j][hf << 5];
        const float4* pb = (const float4*)&bufp[j + 8][hf << 5];
        #pragma unroll
        for (int m = 0; m < 8; m++) { ra[m] = pa[m]; rb[m] = pb[m]; }
    }
    const float y0a = y0s[j];
    const float y0b = y0s[j + 8];

    const float4* wp = (const float4*)(wbuf + ai * W2OFF + hf * WH);
    const int wrow  = hf ? (j + 8) : j;    // the row this lane updates
    const int wslot = ai * W2OFF + (wrow >> 5) * WH + (wrow & 31);
    const float yw  = hf ? y0b : y0a;

    const float cA11 = 0.25f;
    const float cA12 = 0.25f - 0.288675134594812882f;  // 1/4 - sqrt(3)/6
    const float cA21 = 0.25f + 0.288675134594812882f;  // 1/4 + sqrt(3)/6
    const float cA22 = 0.25f;

    float myk = 0.0f;
    #pragma unroll 1
    for (int it = 0; it < NITER; it++) {
        float a0 = 0.f, a1 = 0.f, a2 = 0.f, a3 = 0.f;
        float b0 = 0.f, b1 = 0.f, b2 = 0.f, b3 = 0.f;
        #pragma unroll
        for (int m = 0; m < 8; m++) {
            float4 w = wp[m];          // 4 distinct broadcast addrs, 1 wavefront
            a0 = fmaf(ra[m].x, w.x, a0);
            a1 = fmaf(ra[m].y, w.y, a1);
            a2 = fmaf(ra[m].z, w.z, a2);
            a3 = fmaf(ra[m].w, w.w, a3);
            b0 = fmaf(rb[m].x, w.x, b0);
            b1 = fmaf(rb[m].y, w.y, b1);
            b2 = fmaf(rb[m].z, w.z, b2);
            b3 = fmaf(rb[m].w, w.w, b3);
        }
        float sa = (a0 + a1) + (a2 + a3);      // partial dot, row j
        float sb = (b0 + b1) + (b2 + b3);      // partial dot, row j+8
        sa += __shfl_xor_sync(0xffffffffu, sa, 8);   // combine col-halves
        sb += __shfl_xor_sync(0xffffffffu, sb, 8);
        myk = hf ? sb : sa;                    // k_{ai}[wrow], fully reduced

        if (it == NITER - 1) break;

        // k of the OTHER matrix for the same row lives at lane^16.
        float otherk = __shfl_xor_sync(0xffffffffu, myk, 16);
        float k1v = ai ? otherk : myk;
        float k2v = ai ? myk : otherk;
        // ai==0 lane updates w1[wrow], ai==1 lane updates w2[wrow].
        float val = ai ? fmaf(h, fmaf(cA21, k1v, cA22 * k2v), yw)
                       : fmaf(h, fmaf(cA11, k1v, cA12 * k2v), yw);
        wbuf[wslot] = val;                     // conflict-free (W2OFF=80)
        __syncthreads();                       // one barrier per iteration
    }

    // Publish final k and form y_next.
    (ai ? k2s : k1s)[wrow] = myk;
    __syncthreads();
    if (tid < DD) {
        outY[b * DD + tid] = fmaf(h, 0.5f * (k1s[tid] + k2s[tid]), y0s[tid]);
    }
}

extern "C" void kernel_launch(void* const* d_in, const int* in_sizes, int n_in,
                              void* d_out, int out_size)
{
    const float* A1 = (const float*)d_in[0];   // [B, 64, 64]
    const float* A2 = (const float*)d_in[1];   // [B, 64, 64]
    const float* y0 = (const float*)d_in[2];   // [B, 64]
    const float* h  = (const float*)d_in[3];   // scalar

    float* out  = (float*)d_out;
    const size_t yElems = (size_t)in_sizes[2];         // B*64
    const size_t aElems = (size_t)in_sizes[0];         // B*64*64
    float* outY  = out;                                 // (B, 64)
    float* outA1 = out + yElems;                        // stack[0] = A1
    float* outA2 = outA1 + aElems;                      // stack[1] = A2

    const int B = (int)(yElems / DD);
    glrk4_kernel<<<B, 128>>>(A1, A2, y0, h, outY, outA1, outA2);
    (void)n_in; (void)out_size;
}

// round 9
// speedup vs baseline: 1.9024x; 1.0259x over previous
#include <cuda_runtime.h>
#include <cuda_bf16.h>

// GLRK 4th-order (2-stage Gauss-Legendre) implicit step, B=8192, D=64.
// Picard iteration:  k1 = A1*(y0 + h*(a11 k1 + a12 k2)),
//                    k2 = A2*(y0 + h*(a21 k1 + a22 k2))
//
// R9 = R8 (86.1us) with:
//  - warp-sliced staging: warp wrp stages rows [16wrp,16wrp+16) of A1 & A2 —
//    exactly the rows its lanes consume — so the register tile loads after
//    __syncwarp() instead of a CTA-wide barrier on the full 64KB.
//  - NITER 4 (measured: iteration error contributes ~1e-12 to rel_err at 6;
//    at 4 it is still orders of magnitude under the 1e-3 gate).
// Lane map / single-barrier iteration / fused A copy-out are R8's.

#define DD 64
#define NITER 4
#define ROWPAD 68    // A staging row stride (16B aligned)
#define W2OFF 80     // w2 base offset: 80 mod 32 = 16 -> STS conflict-free
#define WH 36        // half-stride within a w vector (bank shift by 4)

__global__ void __launch_bounds__(128)
glrk4_kernel(const float* __restrict__ gA1,
             const float* __restrict__ gA2,
             const float* __restrict__ gy0,
             const float* __restrict__ gh,
             float* __restrict__ outY,
             float* __restrict__ outA1,
             float* __restrict__ outA2)
{
    __shared__ __align__(16) float buf1[DD][ROWPAD];
    __shared__ __align__(16) float buf2[DD][ROWPAD];
    __shared__ __align__(16) float y0s[DD];
    __shared__ __align__(16) float wbuf[W2OFF + 2 * WH];  // w1 @0, w2 @80
    __shared__ __align__(16) float k1s[DD];
    __shared__ __align__(16) float k2s[DD];

    const int tid = threadIdx.x;
    const int lane = tid & 31;
    const int wrp  = tid >> 5;
    const size_t b = blockIdx.x;
    const float h = __ldg(gh);

    const float4* g1 = (const float4*)(gA1 + b * (DD * DD));
    const float4* g2 = (const float4*)(gA2 + b * (DD * DD));
    float4* o1 = (float4*)(outA1 + b * (DD * DD));
    float4* o2 = (float4*)(outA2 + b * (DD * DD));

    // Warp-sliced staging: warp wrp owns rows [16wrp, 16wrp+16) of both
    // matrices = float4 range [256wrp, 256wrp+256). Coalesced 512B/instr.
    // Fused output copy on the way through.
    {
        const int base = wrp * 256;
        #pragma unroll
        for (int t = 0; t < 8; t++) {
            const int i = base + lane + t * 32;
            const int row = i >> 4;
            const int c   = (i & 15) << 2;
            float4 v1 = g1[i];
            *(float4*)&buf1[row][c] = v1;
            o1[i] = v1;
            float4 v2 = g2[i];
            *(float4*)&buf2[row][c] = v2;
            o2[i] = v2;
        }
    }
    // w/y0 init (w = y0 -> first matvec gives k = R); tiny, done by 2 warps.
    if (tid < DD) {
        float yv = gy0[b * DD + tid];
        y0s[tid] = yv;
        const int wi = (tid >> 5) * WH + (tid & 31);
        wbuf[wi] = yv;            // w1 = y0
        wbuf[W2OFF + wi] = yv;    // w2 = y0
    }
    __syncwarp();   // own-warp staging visible -> load register tile now

    // Lane mapping: j3 = lane[2:0], hf = lane[3], ai = lane[4].
    const int j3 = lane & 7;
    const int hf = (lane >> 3) & 1;
    const int ai = (lane >> 4) & 1;
    const int j  = wrp * 16 + j3;          // owns rows j and j+8 of matrix ai

    float4 ra[8], rb[8];
    {
        const float (*bufp)[ROWPAD] = ai ? buf2 : buf1;
        const float4* pa = (const float4*)&bufp[j][hf << 5];
        const float4* pb = (const float4*)&bufp[j + 8][hf << 5];
        #pragma unroll
        for (int m = 0; m < 8; m++) { ra[m] = pa[m]; rb[m] = pb[m]; }
    }

    __syncthreads();   // w/y0 init visible to all warps
    const float y0a = y0s[j];
    const float y0b = y0s[j + 8];

    const float4* wp = (const float4*)(wbuf + ai * W2OFF + hf * WH);
    const int wrow  = hf ? (j + 8) : j;    // the row this lane updates
    const int wslot = ai * W2OFF + (wrow >> 5) * WH + (wrow & 31);
    const float yw  = hf ? y0b : y0a;

    const float cA11 = 0.25f;
    const float cA12 = 0.25f - 0.288675134594812882f;  // 1/4 - sqrt(3)/6
    const float cA21 = 0.25f + 0.288675134594812882f;  // 1/4 + sqrt(3)/6
    const float cA22 = 0.25f;

    float myk = 0.0f;
    #pragma unroll 1
    for (int it = 0; it < NITER; it++) {
        float a0 = 0.f, a1 = 0.f, a2 = 0.f, a3 = 0.f;
        float b0 = 0.f, b1 = 0.f, b2 = 0.f, b3 = 0.f;
        #pragma unroll
        for (int m = 0; m < 8; m++) {
            float4 w = wp[m];          // 4 distinct broadcast addrs, 1 wavefront
            a0 = fmaf(ra[m].x, w.x, a0);
            a1 = fmaf(ra[m].y, w.y, a1);
            a2 = fmaf(ra[m].z, w.z, a2);
            a3 = fmaf(ra[m].w, w.w, a3);
            b0 = fmaf(rb[m].x, w.x, b0);
            b1 = fmaf(rb[m].y, w.y, b1);
            b2 = fmaf(rb[m].z, w.z, b2);
            b3 = fmaf(rb[m].w, w.w, b3);
        }
        float sa = (a0 + a1) + (a2 + a3);      // partial dot, row j
        float sb = (b0 + b1) + (b2 + b3);      // partial dot, row j+8
        sa += __shfl_xor_sync(0xffffffffu, sa, 8);   // combine col-halves
        sb += __shfl_xor_sync(0xffffffffu, sb, 8);
        myk = hf ? sb : sa;                    // k_{ai}[wrow], fully reduced

        if (it == NITER - 1) break;

        // k of the OTHER matrix for the same row lives at lane^16.
        float otherk = __shfl_xor_sync(0xffffffffu, myk, 16);
        float k1v = ai ? otherk : myk;
        float k2v = ai ? myk : otherk;
        float val = ai ? fmaf(h, fmaf(cA21, k1v, cA22 * k2v), yw)
                       : fmaf(h, fmaf(cA11, k1v, cA12 * k2v), yw);
        wbuf[wslot] = val;                     // conflict-free (W2OFF=80)
        __syncthreads();                       // one barrier per iteration
    }

    // Publish final k and form y_next.
    (ai ? k2s : k1s)[wrow] = myk;
    __syncthreads();
    if (tid < DD) {
        outY[b * DD + tid] = fmaf(h, 0.5f * (k1s[tid] + k2s[tid]), y0s[tid]);
    }
}

extern "C" void kernel_launch(void* const* d_in, const int* in_sizes, int n_in,
                              void* d_out, int out_size)
{
    const float* A1 = (const float*)d_in[0];   // [B, 64, 64]
    const float* A2 = (const float*)d_in[1];   // [B, 64, 64]
    const float* y0 = (const float*)d_in[2];   // [B, 64]
    const float* h  = (const float*)d_in[3];   // scalar

    float* out  = (float*)d_out;
    const size_t yElems = (size_t)in_sizes[2];         // B*64
    const size_t aElems = (size_t)in_sizes[0];         // B*64*64
    float* outY  = out;                                 // (B, 64)
    float* outA1 = out + yElems;                        // stack[0] = A1
    float* outA2 = outA1 + aElems;                      // stack[1] = A2

    const int B = (int)(yElems / DD);
    glrk4_kernel<<<B, 128>>>(A1, A2, y0, h, outY, outA1, outA2);
    (void)n_in; (void)out_size;
}